// round 10
// baseline (speedup 1.0000x reference)
#include <cuda_runtime.h>
#include <cuda_fp16.h>
#include <cstdint>

// ---------------- Problem constants ----------------
#define BQ 256
#define AQ 128
#define FQ 512      // GEMM K
#define DQ 6
#define CQ 512      // GEMM N total
#define BA (BQ*AQ)               // 32768 atoms
#define ROWS_PAD (BA + DQ*128)   // compacted rows incl. per-bucket 128-alignment padding

// ---------------- GEMM tiling ----------------
#define MT 128
#define NT 256
#define KC 64                  // k-tile: 64 fp16 = 128B rows (8x16B chunks, XOR-swizzled)
#define NK (FQ/KC)             // 8
#define NSTG 3
#define OFF_A 0
#define OFF_B 16384            // A: 128 rows x 128B
#define STAGE_B 49152          // + B: 256 rows x 128B
#define DYN_SMEM (NSTG*STAGE_B + 1024)

// ---------------- Static scratch (no runtime allocation) ----------------
__device__ __half g_Ah[(size_t)ROWS_PAD * FQ];        // summed atom features, fp16
__device__ __half g_Wh[(size_t)DQ * CQ * FQ];         // weights [d][n][k] transposed, fp16
__device__ int g_rowatom[ROWS_PAD];
__device__ int g_slotpack[BA];
__device__ int g_counts[DQ];     // transient within prep (reset at end of prep)
__device__ int g_cnt2[DQ];       // stable per-degree counts for gather/gemm
__device__ int g_base[DQ];
__device__ int g_ticket;         // self-resetting block ticket

// ---------------- helpers ----------------
static __device__ __forceinline__ uint32_t smem_u32(const void* p) {
    uint32_t a;
    asm("{ .reg .u64 t; cvta.to.shared.u64 t, %1; cvt.u32.u64 %0, t; }"
        : "=r"(a) : "l"(p));
    return a;
}
static __device__ __forceinline__ void cp16(uint32_t dst, const void* src) {
    asm volatile("cp.async.cg.shared.global [%0], [%1], 16;"
                 :: "r"(dst), "l"(src) : "memory");
}
#define LDSM_X4(r, addr) \
    asm volatile("ldmatrix.sync.aligned.m8n8.x4.shared.b16 {%0,%1,%2,%3}, [%4];" \
                 : "=r"((r)[0]), "=r"((r)[1]), "=r"((r)[2]), "=r"((r)[3]) \
                 : "r"(addr))
static __device__ __forceinline__ void mma_fp16(float* c, const uint32_t* a,
                                                const uint32_t* b) {
    asm volatile(
        "mma.sync.aligned.m16n8k16.row.col.f32.f16.f16.f32 "
        "{%0,%1,%2,%3}, {%4,%5,%6,%7}, {%8,%9}, {%0,%1,%2,%3};"
        : "+f"(c[0]), "+f"(c[1]), "+f"(c[2]), "+f"(c[3])
        : "r"(a[0]), "r"(a[1]), "r"(a[2]), "r"(a[3]), "r"(b[0]), "r"(b[1]));
}
// SW128-style XOR swizzle: offset(row, 16B-chunk j) within a 128B-row tile
static __device__ __forceinline__ uint32_t swz(int row, int j) {
    return (uint32_t)(row * 128 + ((j ^ (row & 7)) * 16));
}

// ---------------------------------------------------------------------------
// Kernel A (fused prep): W transpose + fp16 convert, block-aggregated degree
// bucketing, rowatom init, last-block scan + counter reset.
// ---------------------------------------------------------------------------
__global__ __launch_bounds__(256) void prep_kernel(
    const float* __restrict__ W, const int* __restrict__ bonds)
{
    const int tid = threadIdx.y * 32 + threadIdx.x;
    const int bid = blockIdx.x + blockIdx.y * gridDim.x +
                    blockIdx.z * gridDim.x * gridDim.y;
    const int nblk = gridDim.x * gridDim.y * gridDim.z;

    __shared__ int s_hist[DQ];
    __shared__ int s_basep[DQ];

    if (bid < BA / 256) {
        if (tid < DQ) s_hist[tid] = 0;
        __syncthreads();
        int i = bid * 256 + tid;
        const int* bd = bonds + (size_t)i * DQ;
        int deg = 0;
        #pragma unroll
        for (int k = 0; k < DQ; k++) deg += (bd[k] >= 0);
        if (deg > DQ - 1) deg = DQ - 1;
        int rank = atomicAdd(&s_hist[deg], 1);
        __syncthreads();
        if (tid < DQ)
            s_basep[tid] = atomicAdd(&g_counts[tid], s_hist[tid]);
        __syncthreads();
        g_slotpack[i] = (deg << 16) | (s_basep[deg] + rank);
    }
    for (int j = bid * 256 + tid; j < ROWS_PAD; j += nblk * 256)
        g_rowatom[j] = -1;

    __shared__ float tile[32][33];
    const int d = blockIdx.z;
    const int kb = blockIdx.x * 32, nb = blockIdx.y * 32;
    const int tx = threadIdx.x, ty = threadIdx.y;
    #pragma unroll
    for (int i = 0; i < 4; i++)
        tile[ty + 8 * i][tx] = W[((size_t)d * FQ + kb + ty + 8 * i) * CQ + nb + tx];
    __syncthreads();
    #pragma unroll
    for (int i = 0; i < 4; i++) {
        float v = tile[tx][ty + 8 * i];
        g_Wh[((size_t)d * CQ + nb + ty + 8 * i) * FQ + kb + tx] = __float2half_rn(v);
    }

    __syncthreads();
    if (tid == 0) {
        __threadfence();
        int t = atomicAdd(&g_ticket, 1);
        if (t == nblk - 1) {
            int b = 0;
            #pragma unroll
            for (int dd = 0; dd < DQ; dd++) {
                int c = g_counts[dd];
                g_cnt2[dd] = c;
                g_base[dd] = b;
                b += ((c + 127) >> 7) << 7;
                g_counts[dd] = 0;
            }
            g_ticket = 0;
            __threadfence();
        }
    }
}

// ---------------------------------------------------------------------------
// Kernel B: gather+sum, ONE WARP per atom.
// ---------------------------------------------------------------------------
__global__ __launch_bounds__(256) void gather_kernel(
    const float* __restrict__ atoms, const int* __restrict__ bonds)
{
    const int wid  = blockIdx.x * 8 + (threadIdx.x >> 5);
    const int lane = threadIdx.x & 31;
    const int mol  = wid >> 7;

    int nbv = -1;
    if (lane < DQ) nbv = bonds[(size_t)wid * DQ + lane];

    const int pack = g_slotpack[wid];
    const int pos = g_base[pack >> 16] + (pack & 0xFFFF);
    if (lane == 0) g_rowatom[pos] = wid;

    const float4* A4 = reinterpret_cast<const float4*>(atoms);
    const float4* base = A4 + (size_t)mol * AQ * (FQ / 4);
    const float4* self = A4 + (size_t)wid * (FQ / 4);

    float4 acc[4];
    #pragma unroll
    for (int q = 0; q < 4; q++) acc[q] = self[lane + 32 * q];

    #pragma unroll
    for (int i = 0; i < DQ; i++) {
        int nb = __shfl_sync(0xFFFFFFFFu, nbv, i);
        if (nb >= 0) {
            const float4* np = base + (size_t)nb * (FQ / 4);
            #pragma unroll
            for (int q = 0; q < 4; q++) {
                float4 v = np[lane + 32 * q];
                acc[q].x += v.x; acc[q].y += v.y; acc[q].z += v.z; acc[q].w += v.w;
            }
        }
    }

    #pragma unroll
    for (int q = 0; q < 4; q++) {
        __half2 h01 = __floats2half2_rn(acc[q].x, acc[q].y);
        __half2 h23 = __floats2half2_rn(acc[q].z, acc[q].w);
        size_t o = (size_t)pos * FQ + (lane + 32 * q) * 4;
        reinterpret_cast<__half2*>(g_Ah + o)[0] = h01;
        reinterpret_cast<__half2*>(g_Ah + o)[1] = h23;
    }
}

// ---------------------------------------------------------------------------
// Kernel C: fp16 GEMM via mma.sync.m16n8k16, fp32 accumulate.
// CTA 128x256, 8 warps (2x4), warp tile 64x64; BK=64, 3-stage cp.async,
// 1 CTA/SM (255-reg budget) with fragment double-buffering across ksteps.
// ---------------------------------------------------------------------------
static __device__ __forceinline__ void load_stage(uint32_t sb, int cbase, int wrow,
                                                  int k0, int tid) {
    #pragma unroll
    for (int i = 0; i < 4; i++) {        // A: 1024 16B-chunks
        int c = i * 256 + tid;
        int r = c >> 3, j = c & 7;
        cp16(sb + OFF_A + swz(r, j), g_Ah + (size_t)(cbase + r) * FQ + k0 + j * 8);
    }
    #pragma unroll
    for (int i = 0; i < 8; i++) {        // B: 2048 16B-chunks
        int c = i * 256 + tid;
        int r = c >> 3, j = c & 7;
        cp16(sb + OFF_B + swz(r, j), g_Wh + (size_t)(wrow + r) * FQ + k0 + j * 8);
    }
    asm volatile("cp.async.commit_group;" ::: "memory");
}

__global__ __launch_bounds__(256, 1) void gemm_mma_kernel(
    const float* __restrict__ bias, float* __restrict__ out)
{
    const int d = blockIdx.z;
    const int cnt = g_cnt2[d];
    if ((int)blockIdx.x * MT >= cnt) return;
    const int n0 = blockIdx.y * NT;
    const int cbase = g_base[d] + blockIdx.x * MT;
    const int wrow = d * CQ + n0;

    extern __shared__ char dsm[];
    const uint32_t sb = (smem_u32(dsm) + 1023u) & ~1023u;
    const int tid = threadIdx.x, wid = tid >> 5, lane = tid & 31;
    const int wm = (wid & 1) * 64;       // warp M offset (2 M-warps)
    const int wn = (wid >> 1) * 64;      // warp N offset (4 N-warps)

    // Hoist epilogue row ids.
    const int g  = lane >> 2;
    const int t4 = lane & 3;
    int arow[4][2];
    #pragma unroll
    for (int i = 0; i < 4; i++) {
        const int r0 = cbase + wm + i * 16 + g;
        arow[i][0] = g_rowatom[r0];
        arow[i][1] = g_rowatom[r0 + 8];
    }

    float acc[4][8][4];
    #pragma unroll
    for (int i = 0; i < 4; i++)
        #pragma unroll
        for (int j = 0; j < 8; j++)
            #pragma unroll
            for (int q = 0; q < 4; q++) acc[i][j][q] = 0.f;

    const int a_row = wm + (lane & 15);
    const int a_jlo = lane >> 4;
    const int b_mi  = lane >> 3;
    const int b_rb  = wn + ((b_mi >> 1) * 8) + (lane & 7);
    const int b_jlo = b_mi & 1;

    load_stage(sb, cbase, wrow, 0, tid);
    load_stage(sb + STAGE_B, cbase, wrow, KC, tid);

    uint32_t ah[2][4][4], bh[2][8][2];

    #pragma unroll 1
    for (int c = 0; c < NK; c++) {
        const uint32_t st = sb + (uint32_t)(c % NSTG) * STAGE_B;
        if (c < NK - 1) asm volatile("cp.async.wait_group 1;" ::: "memory");
        else            asm volatile("cp.async.wait_group 0;" ::: "memory");
        __syncthreads();
        if (c + 2 < NK)
            load_stage(sb + (uint32_t)((c + 2) % NSTG) * STAGE_B,
                       cbase, wrow, (c + 2) * KC, tid);

        // Prime fragments for kstep 0.
        #pragma unroll
        for (int i = 0; i < 4; i++)
            LDSM_X4(ah[0][i], st + OFF_A + swz(a_row + i * 16, a_jlo));
        #pragma unroll
        for (int jj = 0; jj < 4; jj++) {
            uint32_t r4[4];
            LDSM_X4(r4, st + OFF_B + swz(b_rb + jj * 16, b_jlo));
            bh[0][jj*2][0] = r4[0]; bh[0][jj*2][1] = r4[1];
            bh[0][jj*2+1][0] = r4[2]; bh[0][jj*2+1][1] = r4[3];
        }

        #pragma unroll
        for (int s = 0; s < 4; s++) {
            const int cur = s & 1, nxt = cur ^ 1;
            if (s < 3) {     // prefetch next kstep's fragments
                #pragma unroll
                for (int i = 0; i < 4; i++)
                    LDSM_X4(ah[nxt][i],
                            st + OFF_A + swz(a_row + i * 16, (s + 1) * 2 + a_jlo));
                #pragma unroll
                for (int jj = 0; jj < 4; jj++) {
                    uint32_t r4[4];
                    LDSM_X4(r4, st + OFF_B + swz(b_rb + jj * 16, (s + 1) * 2 + b_jlo));
                    bh[nxt][jj*2][0] = r4[0]; bh[nxt][jj*2][1] = r4[1];
                    bh[nxt][jj*2+1][0] = r4[2]; bh[nxt][jj*2+1][1] = r4[3];
                }
            }
            #pragma unroll
            for (int i = 0; i < 4; i++)
                #pragma unroll
                for (int j = 0; j < 8; j++)
                    mma_fp16(acc[i][j], ah[cur][i], bh[cur][j]);
        }
    }

    // ---- Epilogue: scatter rows back by atom id, add bias. ----
    float2 bb[8];
    #pragma unroll
    for (int j = 0; j < 8; j++)
        bb[j] = *reinterpret_cast<const float2*>(
                    bias + d * CQ + n0 + wn + j * 8 + t4 * 2);

    #pragma unroll
    for (int i = 0; i < 4; i++) {
        const int a0 = arow[i][0];
        const int a1 = arow[i][1];
        #pragma unroll
        for (int j = 0; j < 8; j++) {
            const int col = n0 + wn + j * 8 + t4 * 2;
            if (a0 >= 0) {
                float2 v = make_float2(acc[i][j][0] + bb[j].x, acc[i][j][1] + bb[j].y);
                *reinterpret_cast<float2*>(out + (size_t)a0 * CQ + col) = v;
            }
            if (a1 >= 0) {
                float2 v = make_float2(acc[i][j][2] + bb[j].x, acc[i][j][3] + bb[j].y);
                *reinterpret_cast<float2*>(out + (size_t)a1 * CQ + col) = v;
            }
        }
    }
}

// ---------------------------------------------------------------------------
// Launch
// ---------------------------------------------------------------------------
extern "C" void kernel_launch(void* const* d_in, const int* in_sizes, int n_in,
                              void* d_out, int out_size)
{
    const float* atoms = (const float*)d_in[0];   // [B, A, F] fp32
    const int*   bonds = (const int*)  d_in[1];   // [B, A, D] int32
    const float* W     = (const float*)d_in[2];   // [D, F, C] fp32
    const float* bias  = (const float*)d_in[3];   // [D, C]    fp32
    float*       out   = (float*)d_out;           // [B, A, C] fp32

    cudaFuncSetAttribute(gemm_mma_kernel,
                         cudaFuncAttributeMaxDynamicSharedMemorySize, DYN_SMEM);

    prep_kernel<<<dim3(FQ / 32, CQ / 32, DQ), dim3(32, 8)>>>(W, bonds);
    gather_kernel<<<BA / 8, 256>>>(atoms, bonds);
    gemm_mma_kernel<<<dim3(BA / MT, CQ / NT, DQ), 256, DYN_SMEM>>>(bias, out);
}

// round 11
// speedup vs baseline: 1.1574x; 1.1574x over previous
#include <cuda_runtime.h>
#include <cuda_fp16.h>
#include <cstdint>

// ---------------- Problem constants ----------------
#define BQ 256
#define AQ 128
#define FQ 512      // GEMM K
#define DQ 6
#define CQ 512      // GEMM N total
#define BA (BQ*AQ)               // 32768 atoms
#define ROWS_PAD (BA + DQ*128)   // compacted rows incl. per-bucket 128-alignment padding

// ---------------- GEMM tiling ----------------
#define MT 128
#define NT 128
#define KC 64                  // k-tile: 64 fp16 = 128B rows (8x16B chunks, XOR-swizzled)
#define NK (FQ/KC)             // 8
#define OFF_A 0
#define OFF_B 16384
#define STAGE_B 32768
#define DYN_SMEM (2*STAGE_B + 1024)

// ---------------- Static scratch (no runtime allocation) ----------------
__device__ __half g_Ah[(size_t)ROWS_PAD * FQ];        // summed atom features, fp16
__device__ __half g_Wh[(size_t)DQ * CQ * FQ];         // weights [d][n][k] transposed, fp16
__device__ int g_rowatom[ROWS_PAD];
__device__ int g_slotpack[BA];
__device__ int g_counts[DQ];     // transient within bucket (reset at end)
__device__ int g_cnt2[DQ];       // stable per-degree counts for gemm
__device__ int g_base[DQ];
__device__ int g_ticket;         // self-resetting block ticket

// ---------------- helpers ----------------
static __device__ __forceinline__ uint32_t smem_u32(const void* p) {
    uint32_t a;
    asm("{ .reg .u64 t; cvta.to.shared.u64 t, %1; cvt.u32.u64 %0, t; }"
        : "=r"(a) : "l"(p));
    return a;
}
static __device__ __forceinline__ void cp16(uint32_t dst, const void* src) {
    asm volatile("cp.async.cg.shared.global [%0], [%1], 16;"
                 :: "r"(dst), "l"(src) : "memory");
}
#define LDSM_X4(r, addr) \
    asm volatile("ldmatrix.sync.aligned.m8n8.x4.shared.b16 {%0,%1,%2,%3}, [%4];" \
                 : "=r"((r)[0]), "=r"((r)[1]), "=r"((r)[2]), "=r"((r)[3]) \
                 : "r"(addr))
static __device__ __forceinline__ void mma_fp16(float* c, const uint32_t* a,
                                                const uint32_t* b) {
    asm volatile(
        "mma.sync.aligned.m16n8k16.row.col.f32.f16.f16.f32 "
        "{%0,%1,%2,%3}, {%4,%5,%6,%7}, {%8,%9}, {%0,%1,%2,%3};"
        : "+f"(c[0]), "+f"(c[1]), "+f"(c[2]), "+f"(c[3])
        : "r"(a[0]), "r"(a[1]), "r"(a[2]), "r"(a[3]), "r"(b[0]), "r"(b[1]));
}
// SW128-style XOR swizzle: offset(row, 16B-chunk j) within a 128B-row tile
static __device__ __forceinline__ uint32_t swz(int row, int j) {
    return (uint32_t)(row * 128 + ((j ^ (row & 7)) * 16));
}

// ---------------------------------------------------------------------------
// Kernel A: bucketing only. 128 blocks x 256 threads.
// Block-aggregated atomics; rowatom init; last-block scan + counter reset.
// ---------------------------------------------------------------------------
__global__ __launch_bounds__(256) void bucket_kernel(const int* __restrict__ bonds) {
    const int tid = threadIdx.x;
    const int bid = blockIdx.x;
    const int nblk = gridDim.x;

    __shared__ int s_hist[DQ];
    __shared__ int s_basep[DQ];

    if (tid < DQ) s_hist[tid] = 0;
    __syncthreads();
    const int i = bid * 256 + tid;
    const int* bd = bonds + (size_t)i * DQ;
    int deg = 0;
    #pragma unroll
    for (int k = 0; k < DQ; k++) deg += (bd[k] >= 0);
    if (deg > DQ - 1) deg = DQ - 1;
    int rank = atomicAdd(&s_hist[deg], 1);
    __syncthreads();
    if (tid < DQ)
        s_basep[tid] = atomicAdd(&g_counts[tid], s_hist[tid]);
    __syncthreads();
    g_slotpack[i] = (deg << 16) | (s_basep[deg] + rank);

    // rowatom init spread over the 128 blocks
    for (int j = bid * 256 + tid; j < ROWS_PAD; j += nblk * 256)
        g_rowatom[j] = -1;

    __syncthreads();
    if (tid == 0) {
        __threadfence();
        int t = atomicAdd(&g_ticket, 1);
        if (t == nblk - 1) {
            int b = 0;
            #pragma unroll
            for (int dd = 0; dd < DQ; dd++) {
                int c = g_counts[dd];
                g_cnt2[dd] = c;
                g_base[dd] = b;
                b += ((c + 127) >> 7) << 7;
                g_counts[dd] = 0;          // ready for next graph replay
            }
            g_ticket = 0;                  // self-reset
            __threadfence();
        }
    }
}

// ---------------------------------------------------------------------------
// Kernel B (fused): blocks [0, 4096) do warp-per-atom gather+sum -> fp16;
// blocks [4096, 5632) do the W [d][k][n] -> [d][n][k] fp16 transpose.
// The two halves are independent and overlap on the machine.
// ---------------------------------------------------------------------------
#define GATHER_BLOCKS (BA / 8)                 // 4096
#define WT_BLOCKS (DQ * (FQ / 32) * (CQ / 32)) // 1536

__global__ __launch_bounds__(256) void mid_kernel(
    const float* __restrict__ atoms, const int* __restrict__ bonds,
    const float* __restrict__ W)
{
    if (blockIdx.x < GATHER_BLOCKS) {
        // ---- gather: one warp per atom ----
        const int wid  = blockIdx.x * 8 + (threadIdx.x >> 5);
        const int lane = threadIdx.x & 31;
        const int mol  = wid >> 7;

        int nbv = -1;
        if (lane < DQ) nbv = bonds[(size_t)wid * DQ + lane];

        const int pack = g_slotpack[wid];
        const int pos = g_base[pack >> 16] + (pack & 0xFFFF);
        if (lane == 0) g_rowatom[pos] = wid;

        const float4* A4 = reinterpret_cast<const float4*>(atoms);
        const float4* base = A4 + (size_t)mol * AQ * (FQ / 4);
        const float4* self = A4 + (size_t)wid * (FQ / 4);

        float4 acc[4];
        #pragma unroll
        for (int q = 0; q < 4; q++) acc[q] = self[lane + 32 * q];

        #pragma unroll
        for (int i = 0; i < DQ; i++) {
            int nb = __shfl_sync(0xFFFFFFFFu, nbv, i);
            if (nb >= 0) {
                const float4* np = base + (size_t)nb * (FQ / 4);
                #pragma unroll
                for (int q = 0; q < 4; q++) {
                    float4 v = np[lane + 32 * q];
                    acc[q].x += v.x; acc[q].y += v.y; acc[q].z += v.z; acc[q].w += v.w;
                }
            }
        }

        #pragma unroll
        for (int q = 0; q < 4; q++) {
            __half2 h01 = __floats2half2_rn(acc[q].x, acc[q].y);
            __half2 h23 = __floats2half2_rn(acc[q].z, acc[q].w);
            size_t o = (size_t)pos * FQ + (lane + 32 * q) * 4;
            reinterpret_cast<__half2*>(g_Ah + o)[0] = h01;
            reinterpret_cast<__half2*>(g_Ah + o)[1] = h23;
        }
    } else {
        // ---- W transpose 32x32 tile -> fp16 [d][n][k] ----
        __shared__ float tile[32][33];
        const int b2 = blockIdx.x - GATHER_BLOCKS;        // 0..1535
        const int d   = b2 >> 8;                          // / 256
        const int rem = b2 & 255;
        const int kb = (rem & 15) * 32;
        const int nb = (rem >> 4) * 32;
        const int tx = threadIdx.x & 31;
        const int ty = threadIdx.x >> 5;                  // 0..7
        #pragma unroll
        for (int i = 0; i < 4; i++)
            tile[ty + 8 * i][tx] = W[((size_t)d * FQ + kb + ty + 8 * i) * CQ + nb + tx];
        __syncthreads();
        #pragma unroll
        for (int i = 0; i < 4; i++) {
            float v = tile[tx][ty + 8 * i];
            g_Wh[((size_t)d * CQ + nb + ty + 8 * i) * FQ + kb + tx] = __float2half_rn(v);
        }
    }
}

// ---------------------------------------------------------------------------
// Kernel C: fp16 GEMM via mma.sync.m16n8k16, fp32 accumulate.
// CTA 128x128, 8 warps (2x4), warp tile 64x32; BK=64, 2-stage cp.async.
// (Byte-exact measured-best R8 configuration — do not restructure.)
// ---------------------------------------------------------------------------
static __device__ __forceinline__ void load_stage(uint32_t sb, int cbase, int wrow,
                                                  int k0, int tid) {
    #pragma unroll
    for (int i = 0; i < 4; i++) {
        int c = i * 256 + tid;          // 1024 16B-chunks per 16KB tile
        int r = c >> 3, j = c & 7;
        uint32_t off = swz(r, j);
        cp16(sb + OFF_A + off, g_Ah + (size_t)(cbase + r) * FQ + k0 + j * 8);
        cp16(sb + OFF_B + off, g_Wh + (size_t)(wrow + r) * FQ + k0 + j * 8);
    }
    asm volatile("cp.async.commit_group;" ::: "memory");
}

__global__ __launch_bounds__(256, 2) void gemm_mma_kernel(
    const float* __restrict__ bias, float* __restrict__ out)
{
    const int d = blockIdx.z;
    const int cnt = g_cnt2[d];
    if ((int)blockIdx.x * MT >= cnt) return;
    const int n0 = blockIdx.y * NT;
    const int cbase = g_base[d] + blockIdx.x * MT;
    const int wrow = d * CQ + n0;

    extern __shared__ char dsm[];
    const uint32_t sb = (smem_u32(dsm) + 1023u) & ~1023u;
    const int tid = threadIdx.x, wid = tid >> 5, lane = tid & 31;
    const int wm = (wid & 1) * 64;       // warp M offset in tile
    const int wn = (wid >> 1) * 32;      // warp N offset in tile

    // Hoist epilogue row ids.
    const int g  = lane >> 2;
    const int t4 = lane & 3;
    int arow[4][2];
    #pragma unroll
    for (int i = 0; i < 4; i++) {
        const int r0 = cbase + wm + i * 16 + g;
        arow[i][0] = g_rowatom[r0];
        arow[i][1] = g_rowatom[r0 + 8];
    }

    float acc[4][4][4];
    #pragma unroll
    for (int i = 0; i < 4; i++)
        #pragma unroll
        for (int j = 0; j < 4; j++)
            #pragma unroll
            for (int q = 0; q < 4; q++) acc[i][j][q] = 0.f;

    const int a_row = wm + (lane & 15);
    const int a_jlo = lane >> 4;
    const int b_mi  = lane >> 3;
    const int b_rb  = wn + ((b_mi >> 1) * 8) + (lane & 7);
    const int b_jlo = b_mi & 1;

    load_stage(sb, cbase, wrow, 0, tid);
    load_stage(sb + STAGE_B, cbase, wrow, KC, tid);

    #pragma unroll 1
    for (int c = 0; c < NK; c++) {
        const uint32_t st = sb + (c & 1) * STAGE_B;
        if (c < NK - 1) asm volatile("cp.async.wait_group 1;" ::: "memory");
        else            asm volatile("cp.async.wait_group 0;" ::: "memory");
        __syncthreads();

        #pragma unroll
        for (int s = 0; s < 4; s++) {               // 4 x k16 per k-tile
            uint32_t ah[4][4], bh[4][2];
            #pragma unroll
            for (int i = 0; i < 4; i++) {
                int row = a_row + i * 16;
                LDSM_X4(ah[i], st + OFF_A + swz(row, s * 2 + a_jlo));
            }
            #pragma unroll
            for (int jj = 0; jj < 2; jj++) {
                int row = b_rb + jj * 16;
                uint32_t r4[4];
                LDSM_X4(r4, st + OFF_B + swz(row, s * 2 + b_jlo));
                bh[jj*2][0] = r4[0]; bh[jj*2][1] = r4[1];
                bh[jj*2+1][0] = r4[2]; bh[jj*2+1][1] = r4[3];
            }
            #pragma unroll
            for (int i = 0; i < 4; i++)
                #pragma unroll
                for (int j = 0; j < 4; j++)
                    mma_fp16(acc[i][j], ah[i], bh[j]);
        }
        __syncthreads();
        if (c + 2 < NK)
            load_stage(sb + (c & 1) * STAGE_B, cbase, wrow, (c + 2) * KC, tid);
    }

    // ---- Epilogue: scatter rows back by atom id, add bias. ----
    float2 bb[4];
    #pragma unroll
    for (int j = 0; j < 4; j++)
        bb[j] = *reinterpret_cast<const float2*>(
                    bias + d * CQ + n0 + wn + j * 8 + t4 * 2);

    #pragma unroll
    for (int i = 0; i < 4; i++) {
        const int a0 = arow[i][0];
        const int a1 = arow[i][1];
        #pragma unroll
        for (int j = 0; j < 4; j++) {
            const int col = n0 + wn + j * 8 + t4 * 2;
            if (a0 >= 0) {
                float2 v = make_float2(acc[i][j][0] + bb[j].x, acc[i][j][1] + bb[j].y);
                *reinterpret_cast<float2*>(out + (size_t)a0 * CQ + col) = v;
            }
            if (a1 >= 0) {
                float2 v = make_float2(acc[i][j][2] + bb[j].x, acc[i][j][3] + bb[j].y);
                *reinterpret_cast<float2*>(out + (size_t)a1 * CQ + col) = v;
            }
        }
    }
}

// ---------------------------------------------------------------------------
// Launch
// ---------------------------------------------------------------------------
extern "C" void kernel_launch(void* const* d_in, const int* in_sizes, int n_in,
                              void* d_out, int out_size)
{
    const float* atoms = (const float*)d_in[0];   // [B, A, F] fp32
    const int*   bonds = (const int*)  d_in[1];   // [B, A, D] int32
    const float* W     = (const float*)d_in[2];   // [D, F, C] fp32
    const float* bias  = (const float*)d_in[3];   // [D, C]    fp32
    float*       out   = (float*)d_out;           // [B, A, C] fp32

    cudaFuncSetAttribute(gemm_mma_kernel,
                         cudaFuncAttributeMaxDynamicSharedMemorySize, DYN_SMEM);

    bucket_kernel<<<BA / 256, 256>>>(bonds);
    mid_kernel<<<GATHER_BLOCKS + WT_BLOCKS, 256>>>(atoms, bonds, W);
    gemm_mma_kernel<<<dim3(BA / MT, CQ / NT, DQ), 256, DYN_SMEM>>>(bias, out);
}